// round 1
// baseline (speedup 1.0000x reference)
#include <cuda_runtime.h>
#include <cuda_bf16.h>

#define N_TOK 8192
#define DMODEL 1024
#define DFF 4096
#define NEXP 8
#define NPAIR (N_TOK * 2)
#define EPSF 1.1920928955078125e-07f

// ---------------- scratch (static device globals; no allocations) ----------------
__device__ float g_h[(size_t)N_TOK * DMODEL];     // 32 MB   rmsnorm'd hidden
__device__ float g_y[(size_t)N_TOK * DMODEL];     // 32 MB   pre-out-proj
__device__ float g_T[(size_t)NPAIR * DFF];        // 256 MB  silu(g)*u per pair
__device__ float g_Oe[(size_t)NPAIR * DMODEL];    // 64 MB   down-proj per pair
__device__ int   g_cnt[NEXP];
__device__ int   g_off[NEXP + 1];
__device__ int   g_cur[NEXP];
__device__ int   g_pairtok[NPAIR];
__device__ int   g_slotof[NPAIR];
__device__ int   g_topidx[NPAIR];
__device__ float g_topgate[NPAIR];

// ---------------- tiny kernels ----------------
__global__ void init_counts() {
    if (threadIdx.x < NEXP) g_cnt[threadIdx.x] = 0;
}

__global__ void scan_offsets() {
    if (threadIdx.x == 0) {
        int s = 0;
        for (int e = 0; e < NEXP; e++) { g_off[e] = s; s += g_cnt[e]; }
        g_off[NEXP] = s;
    }
    if (threadIdx.x < NEXP) g_cur[threadIdx.x] = 0;
}

__global__ void scatter_pairs() {
    int t = blockIdx.x * blockDim.x + threadIdx.x;
    if (t >= N_TOK) return;
    #pragma unroll
    for (int k = 0; k < 2; k++) {
        int e = g_topidx[2 * t + k];
        int p = atomicAdd(&g_cur[e], 1);
        int slot = g_off[e] + p;
        g_pairtok[slot] = t;
        g_slotof[2 * t + k] = slot;
    }
}

// ---------------- rmsnorm over rows of length DMODEL (256 thr, float4) ----------------
__global__ void rmsnorm_rows(const float* __restrict__ X,
                             const float* __restrict__ w,
                             float* __restrict__ Y)
{
    int row = blockIdx.x;
    int tid = threadIdx.x;                       // 256
    const float4* xr = (const float4*)(X + (long long)row * DMODEL);
    float4 v = xr[tid];
    float ss = v.x * v.x + v.y * v.y + v.z * v.z + v.w * v.w;
    __shared__ float red[8];
    #pragma unroll
    for (int o = 16; o; o >>= 1) ss += __shfl_xor_sync(0xffffffffu, ss, o);
    if ((tid & 31) == 0) red[tid >> 5] = ss;
    __syncthreads();
    float tot = red[0] + red[1] + red[2] + red[3] + red[4] + red[5] + red[6] + red[7];
    float r = rsqrtf(tot * (1.0f / DMODEL) + EPSF);
    float4 wv = ((const float4*)w)[tid];
    float4 o4;
    o4.x = v.x * r * wv.x; o4.y = v.y * r * wv.y;
    o4.z = v.z * r * wv.z; o4.w = v.w * r * wv.w;
    ((float4*)(Y + (long long)row * DMODEL))[tid] = o4;
}

// ---------------- router: one warp per token ----------------
__global__ void router_kernel(const float* __restrict__ h,
                              const float* __restrict__ Wr,
                              const float* __restrict__ bias)
{
    int warp = (blockIdx.x * blockDim.x + threadIdx.x) >> 5;
    int lane = threadIdx.x & 31;
    if (warp >= N_TOK) return;
    const float* hr = h + (long long)warp * DMODEL;
    float acc[NEXP];
    #pragma unroll
    for (int e = 0; e < NEXP; e++) acc[e] = 0.0f;
    for (int d = lane; d < DMODEL; d += 32) {
        float hv = hr[d];
        #pragma unroll
        for (int e = 0; e < NEXP; e++) acc[e] += hv * Wr[e * DMODEL + d];
    }
    #pragma unroll
    for (int e = 0; e < NEXP; e++) {
        #pragma unroll
        for (int o = 16; o; o >>= 1) acc[e] += __shfl_xor_sync(0xffffffffu, acc[e], o);
    }
    if (lane == 0) {
        float b0 = -1e30f, b1 = -1e30f; int i0 = 0, i1 = 0;
        #pragma unroll
        for (int e = 0; e < NEXP; e++) {
            float v = acc[e] + bias[e];
            if (v > b0) { b1 = b0; i1 = i0; b0 = v; i0 = e; }
            else if (v > b1) { b1 = v; i1 = e; }
        }
        float l0 = acc[i0], l1 = acc[i1];
        float m = fmaxf(l0, l1);
        float e0 = expf(l0 - m), e1 = expf(l1 - m);
        float inv = 1.0f / (e0 + e1);
        g_topidx[2 * warp] = i0;  g_topidx[2 * warp + 1] = i1;
        g_topgate[2 * warp] = e0 * inv; g_topgate[2 * warp + 1] = e1 * inv;
        atomicAdd(&g_cnt[i0], 1);
        atomicAdd(&g_cnt[i1], 1);
    }
}

// ---------------- generic SGEMM: C[M,N] = A[M,K] * B[N,K]^T ----------------
// 128x128 tile, BK=8, 256 threads, 8x8 per thread, smem double-buffered.
// GROUPED=1: blockIdx.z = expert, rows come from d_off[e]..d_off[e+1].
template<int GROUPED>
__global__ __launch_bounds__(256) void gemm128_nt(
    const float* __restrict__ A, const float* __restrict__ B, float* __restrict__ C,
    int M, int Ncols, int Kdim,
    const int* __restrict__ gather, const int* __restrict__ d_off, long long strideB)
{
    int rowBase = 0, Mloc = M;
    const float* Bp = B;
    if (GROUPED) {
        int e = blockIdx.z;
        rowBase = d_off[e];
        Mloc = d_off[e + 1] - rowBase;
        Bp = B + (long long)e * strideB;
    }
    int bm = blockIdx.x * 128;
    if (bm >= Mloc) return;
    int bn = blockIdx.y * 128;

    __shared__ __align__(16) float As[2][8][128];
    __shared__ __align__(16) float Bs[2][8][128];

    int tid = threadIdx.x;
    int tx = tid & 15;
    int ty = tid >> 4;
    int lr = tid >> 1;
    int lc = (tid & 1) * 4;

    int arl = bm + lr; if (arl >= Mloc) arl = Mloc - 1;
    int gidx = rowBase + arl;
    long long arow = gather ? (long long)gather[gidx] : (long long)gidx;
    const float* Arow = A + arow * Kdim + lc;
    const float* Brow = Bp + (long long)(bn + lr) * Kdim + lc;

    float acc[8][8];
    #pragma unroll
    for (int i = 0; i < 8; i++)
        #pragma unroll
        for (int j = 0; j < 8; j++) acc[i][j] = 0.0f;

    int ntiles = Kdim >> 3;
    float4 ra = *(const float4*)(Arow);
    float4 rb = *(const float4*)(Brow);
    As[0][lc + 0][lr] = ra.x; As[0][lc + 1][lr] = ra.y;
    As[0][lc + 2][lr] = ra.z; As[0][lc + 3][lr] = ra.w;
    Bs[0][lc + 0][lr] = rb.x; Bs[0][lc + 1][lr] = rb.y;
    Bs[0][lc + 2][lr] = rb.z; Bs[0][lc + 3][lr] = rb.w;

    for (int kt = 0; kt < ntiles; kt++) {
        __syncthreads();
        int buf = kt & 1;
        bool more = (kt + 1) < ntiles;
        if (more) {
            ra = *(const float4*)(Arow + (kt + 1) * 8);
            rb = *(const float4*)(Brow + (kt + 1) * 8);
        }
        #pragma unroll
        for (int kk = 0; kk < 8; kk++) {
            float4 a0 = *(const float4*)&As[buf][kk][ty * 8];
            float4 a1 = *(const float4*)&As[buf][kk][ty * 8 + 4];
            float4 b0 = *(const float4*)&Bs[buf][kk][tx * 8];
            float4 b1 = *(const float4*)&Bs[buf][kk][tx * 8 + 4];
            float av[8] = {a0.x, a0.y, a0.z, a0.w, a1.x, a1.y, a1.z, a1.w};
            float bv[8] = {b0.x, b0.y, b0.z, b0.w, b1.x, b1.y, b1.z, b1.w};
            #pragma unroll
            for (int i = 0; i < 8; i++)
                #pragma unroll
                for (int j = 0; j < 8; j++) acc[i][j] += av[i] * bv[j];
        }
        if (more) {
            int nb = buf ^ 1;
            As[nb][lc + 0][lr] = ra.x; As[nb][lc + 1][lr] = ra.y;
            As[nb][lc + 2][lr] = ra.z; As[nb][lc + 3][lr] = ra.w;
            Bs[nb][lc + 0][lr] = rb.x; Bs[nb][lc + 1][lr] = rb.y;
            Bs[nb][lc + 2][lr] = rb.z; Bs[nb][lc + 3][lr] = rb.w;
        }
    }

    #pragma unroll
    for (int i = 0; i < 8; i++) {
        int r = bm + ty * 8 + i;
        if (r < Mloc) {
            float* Crow = C + (long long)(rowBase + r) * Ncols + bn + tx * 8;
            float4 c0 = make_float4(acc[i][0], acc[i][1], acc[i][2], acc[i][3]);
            float4 c1 = make_float4(acc[i][4], acc[i][5], acc[i][6], acc[i][7]);
            *(float4*)(Crow) = c0;
            *(float4*)(Crow + 4) = c1;
        }
    }
}

// ---------------- fused gate/up GEMM: T[slot,f] = silu(h.Wg[e][f]) * (h.Wu[e][f]) ----------------
// 128x64 tile, BK=8, 256 threads, per-thread 8x4 for each of the two accumulators.
__global__ __launch_bounds__(256) void gemm_gateup(
    const float* __restrict__ H, const float* __restrict__ Wg,
    const float* __restrict__ Wu, float* __restrict__ T,
    const int* __restrict__ pairtok, const int* __restrict__ d_off)
{
    int e = blockIdx.z;
    int rowBase = d_off[e];
    int Mloc = d_off[e + 1] - rowBase;
    int bm = blockIdx.x * 128;
    if (bm >= Mloc) return;
    int bn = blockIdx.y * 64;

    const float* Bg = Wg + (long long)e * DFF * DMODEL;
    const float* Bu = Wu + (long long)e * DFF * DMODEL;

    __shared__ __align__(16) float As[2][8][128];
    __shared__ __align__(16) float Gs[2][8][64];
    __shared__ __align__(16) float Us[2][8][64];

    int tid = threadIdx.x;
    int tx = tid & 15;   // cols tx*4 .. tx*4+3
    int ty = tid >> 4;   // rows ty*8 ..
    int lr = tid >> 1;
    int lc = (tid & 1) * 4;

    int arl = bm + lr; if (arl >= Mloc) arl = Mloc - 1;
    int tok = pairtok[rowBase + arl];
    const float* Arow = H + (long long)tok * DMODEL + lc;

    int grp = tid >> 7;          // 0 -> Wg, 1 -> Wu
    int t2 = tid & 127;
    int br = t2 >> 1;            // 0..63
    int bc = (t2 & 1) * 4;
    const float* Brow = (grp ? Bu : Bg) + (long long)(bn + br) * DMODEL + bc;

    float accg[8][4], accu[8][4];
    #pragma unroll
    for (int i = 0; i < 8; i++)
        #pragma unroll
        for (int j = 0; j < 4; j++) { accg[i][j] = 0.0f; accu[i][j] = 0.0f; }

    int ntiles = DMODEL >> 3;
    float4 ra = *(const float4*)(Arow);
    float4 rb = *(const float4*)(Brow);
    As[0][lc + 0][lr] = ra.x; As[0][lc + 1][lr] = ra.y;
    As[0][lc + 2][lr] = ra.z; As[0][lc + 3][lr] = ra.w;
    if (grp == 0) {
        Gs[0][bc + 0][br] = rb.x; Gs[0][bc + 1][br] = rb.y;
        Gs[0][bc + 2][br] = rb.z; Gs[0][bc + 3][br] = rb.w;
    } else {
        Us[0][bc + 0][br] = rb.x; Us[0][bc + 1][br] = rb.y;
        Us[0][bc + 2][br] = rb.z; Us[0][bc + 3][br] = rb.w;
    }

    for (int kt = 0; kt < ntiles; kt++) {
        __syncthreads();
        int buf = kt & 1;
        bool more = (kt + 1) < ntiles;
        if (more) {
            ra = *(const float4*)(Arow + (kt + 1) * 8);
            rb = *(const float4*)(Brow + (kt + 1) * 8);
        }
        #pragma unroll
        for (int kk = 0; kk < 8; kk++) {
            float4 a0 = *(const float4*)&As[buf][kk][ty * 8];
            float4 a1 = *(const float4*)&As[buf][kk][ty * 8 + 4];
            float4 gg = *(const float4*)&Gs[buf][kk][tx * 4];
            float4 uu = *(const float4*)&Us[buf][kk][tx * 4];
            float av[8] = {a0.x, a0.y, a0.z, a0.w, a1.x, a1.y, a1.z, a1.w};
            float gv[4] = {gg.x, gg.y, gg.z, gg.w};
            float uv[4] = {uu.x, uu.y, uu.z, uu.w};
            #pragma unroll
            for (int i = 0; i < 8; i++)
                #pragma unroll
                for (int j = 0; j < 4; j++) {
                    accg[i][j] += av[i] * gv[j];
                    accu[i][j] += av[i] * uv[j];
                }
        }
        if (more) {
            int nb = buf ^ 1;
            As[nb][lc + 0][lr] = ra.x; As[nb][lc + 1][lr] = ra.y;
            As[nb][lc + 2][lr] = ra.z; As[nb][lc + 3][lr] = ra.w;
            if (grp == 0) {
                Gs[nb][bc + 0][br] = rb.x; Gs[nb][bc + 1][br] = rb.y;
                Gs[nb][bc + 2][br] = rb.z; Gs[nb][bc + 3][br] = rb.w;
            } else {
                Us[nb][bc + 0][br] = rb.x; Us[nb][bc + 1][br] = rb.y;
                Us[nb][bc + 2][br] = rb.z; Us[nb][bc + 3][br] = rb.w;
            }
        }
    }

    #pragma unroll
    for (int i = 0; i < 8; i++) {
        int r = bm + ty * 8 + i;
        if (r < Mloc) {
            float* Trow = T + (long long)(rowBase + r) * DFF + bn + tx * 4;
            float4 o4;
            float g0, u0;
            g0 = accg[i][0]; u0 = accu[i][0]; o4.x = (g0 / (1.0f + __expf(-g0))) * u0;
            g0 = accg[i][1]; u0 = accu[i][1]; o4.y = (g0 / (1.0f + __expf(-g0))) * u0;
            g0 = accg[i][2]; u0 = accu[i][2]; o4.z = (g0 / (1.0f + __expf(-g0))) * u0;
            g0 = accg[i][3]; u0 = accu[i][3]; o4.w = (g0 / (1.0f + __expf(-g0))) * u0;
            *(float4*)Trow = o4;
        }
    }
}

// ---------------- combine: per-token expert-rmsnorm, gate-weighted sum, out-rmsnorm ----------------
__global__ void combine_rows(const float* __restrict__ enorm,
                             const float* __restrict__ outnorm)
{
    int t = blockIdx.x;
    int tid = threadIdx.x;   // 256
    int s0 = g_slotof[2 * t], s1 = g_slotof[2 * t + 1];
    int e0 = g_topidx[2 * t], e1 = g_topidx[2 * t + 1];
    float gg0 = g_topgate[2 * t], gg1 = g_topgate[2 * t + 1];

    float4 a = ((const float4*)(g_Oe + (long long)s0 * DMODEL))[tid];
    float4 b = ((const float4*)(g_Oe + (long long)s1 * DMODEL))[tid];
    float ssa = a.x * a.x + a.y * a.y + a.z * a.z + a.w * a.w;
    float ssb = b.x * b.x + b.y * b.y + b.z * b.z + b.w * b.w;

    __shared__ float redA[8], redB[8], redC[8];
    #pragma unroll
    for (int o = 16; o; o >>= 1) {
        ssa += __shfl_xor_sync(0xffffffffu, ssa, o);
        ssb += __shfl_xor_sync(0xffffffffu, ssb, o);
    }
    if ((tid & 31) == 0) { redA[tid >> 5] = ssa; redB[tid >> 5] = ssb; }
    __syncthreads();
    float ta = redA[0] + redA[1] + redA[2] + redA[3] + redA[4] + redA[5] + redA[6] + redA[7];
    float tb = redB[0] + redB[1] + redB[2] + redB[3] + redB[4] + redB[5] + redB[6] + redB[7];
    float r0 = rsqrtf(ta * (1.0f / DMODEL) + EPSF) * gg0;
    float r1 = rsqrtf(tb * (1.0f / DMODEL) + EPSF) * gg1;

    float4 w0 = ((const float4*)(enorm + (long long)e0 * DMODEL))[tid];
    float4 w1 = ((const float4*)(enorm + (long long)e1 * DMODEL))[tid];
    float4 c;
    c.x = a.x * r0 * w0.x + b.x * r1 * w1.x;
    c.y = a.y * r0 * w0.y + b.y * r1 * w1.y;
    c.z = a.z * r0 * w0.z + b.z * r1 * w1.z;
    c.w = a.w * r0 * w0.w + b.w * r1 * w1.w;

    float ssc = c.x * c.x + c.y * c.y + c.z * c.z + c.w * c.w;
    #pragma unroll
    for (int o = 16; o; o >>= 1) ssc += __shfl_xor_sync(0xffffffffu, ssc, o);
    if ((tid & 31) == 0) redC[tid >> 5] = ssc;
    __syncthreads();
    float tc = redC[0] + redC[1] + redC[2] + redC[3] + redC[4] + redC[5] + redC[6] + redC[7];
    float rc = rsqrtf(tc * (1.0f / DMODEL) + EPSF);

    float4 wo = ((const float4*)outnorm)[tid];
    float4 o4;
    o4.x = c.x * rc * wo.x; o4.y = c.y * rc * wo.y;
    o4.z = c.z * rc * wo.z; o4.w = c.w * rc * wo.w;
    ((float4*)(g_y + (long long)t * DMODEL))[tid] = o4;
}

// ---------------- launch ----------------
extern "C" void kernel_launch(void* const* d_in, const int* in_sizes, int n_in,
                              void* d_out, int out_size)
{
    const float* s          = (const float*)d_in[0];
    const float* W_in       = (const float*)d_in[1];
    const float* in_norm_w  = (const float*)d_in[2];
    const float* Wr         = (const float*)d_in[3];
    const float* expert_bias= (const float*)d_in[4];
    const float* Wg         = (const float*)d_in[5];
    const float* Wu         = (const float*)d_in[6];
    const float* Wd         = (const float*)d_in[7];
    const float* enorm_w    = (const float*)d_in[8];
    const float* out_norm_w = (const float*)d_in[9];
    const float* W_out      = (const float*)d_in[10];
    float* out = (float*)d_out;

    void *p_h, *p_y, *p_T, *p_Oe, *p_off, *p_pairtok;
    cudaGetSymbolAddress(&p_h, g_h);
    cudaGetSymbolAddress(&p_y, g_y);
    cudaGetSymbolAddress(&p_T, g_T);
    cudaGetSymbolAddress(&p_Oe, g_Oe);
    cudaGetSymbolAddress(&p_off, g_off);
    cudaGetSymbolAddress(&p_pairtok, g_pairtok);
    float* h_ptr  = (float*)p_h;
    float* y_ptr  = (float*)p_y;
    float* T_ptr  = (float*)p_T;
    float* Oe_ptr = (float*)p_Oe;
    int* off_ptr  = (int*)p_off;
    int* ptok_ptr = (int*)p_pairtok;

    init_counts<<<1, 32>>>();

    // h_pre = s @ W_in^T
    gemm128_nt<0><<<dim3(N_TOK / 128, DMODEL / 128, 1), 256>>>(
        s, W_in, h_ptr, N_TOK, DMODEL, DMODEL, nullptr, nullptr, 0);

    // h = rmsnorm(h_pre) (in place)
    rmsnorm_rows<<<N_TOK, 256>>>(h_ptr, in_norm_w, h_ptr);

    // router + top-2 + counts
    router_kernel<<<(N_TOK * 32) / 256, 256>>>(h_ptr, Wr, expert_bias);

    scan_offsets<<<1, 32>>>();
    scatter_pairs<<<N_TOK / 256, 256>>>();

    // T = silu(h Wg^T) * (h Wu^T), grouped by expert
    gemm_gateup<<<dim3(NPAIR / 128, DFF / 64, NEXP), 256>>>(
        h_ptr, Wg, Wu, T_ptr, ptok_ptr, off_ptr);

    // Oe = T @ Wd[e]^T, grouped by expert
    gemm128_nt<1><<<dim3(NPAIR / 128, DMODEL / 128, NEXP), 256>>>(
        T_ptr, Wd, Oe_ptr, 0, DMODEL, DFF, nullptr, off_ptr,
        (long long)DMODEL * DFF);

    // per-token combine (expert rmsnorm + gates + output rmsnorm) -> g_y
    combine_rows<<<N_TOK, 256>>>(enorm_w, out_norm_w);

    // s_hat = y @ W_out^T
    gemm128_nt<0><<<dim3(N_TOK / 128, DMODEL / 128, 1), 256>>>(
        y_ptr, W_out, out, N_TOK, DMODEL, DMODEL, nullptr, nullptr, 0);
}

// round 2
// speedup vs baseline: 1.0013x; 1.0013x over previous
#include <cuda_runtime.h>
#include <cuda_bf16.h>

#define N_TOK 8192
#define DMODEL 1024
#define DFF 4096
#define NEXP 8
#define NPAIR (N_TOK * 2)
#define EPSF 1.1920928955078125e-07f

// ---------------- scratch (static device globals; no allocations) ----------------
__device__ float g_h[(size_t)N_TOK * DMODEL];     // 32 MB   rmsnorm'd hidden
__device__ float g_y[(size_t)N_TOK * DMODEL];     // 32 MB   pre-out-proj
__device__ float g_T[(size_t)NPAIR * DFF];        // 256 MB  silu(g)*u per pair
__device__ float g_Oe[(size_t)NPAIR * DMODEL];    // 64 MB   down-proj per pair
__device__ int   g_cnt[NEXP];
__device__ int   g_off[NEXP + 1];
__device__ int   g_cur[NEXP];
__device__ int   g_pairtok[NPAIR];
__device__ int   g_slotof[NPAIR];
__device__ int   g_topidx[NPAIR];
__device__ float g_topgate[NPAIR];

// ---------------- tiny kernels ----------------
__global__ void init_counts() {
    if (threadIdx.x < NEXP) g_cnt[threadIdx.x] = 0;
}

__global__ void scan_offsets() {
    if (threadIdx.x == 0) {
        int s = 0;
        for (int e = 0; e < NEXP; e++) { g_off[e] = s; s += g_cnt[e]; }
        g_off[NEXP] = s;
    }
    if (threadIdx.x < NEXP) g_cur[threadIdx.x] = 0;
}

__global__ void scatter_pairs() {
    int t = blockIdx.x * blockDim.x + threadIdx.x;
    if (t >= N_TOK) return;
    #pragma unroll
    for (int k = 0; k < 2; k++) {
        int e = g_topidx[2 * t + k];
        int p = atomicAdd(&g_cur[e], 1);
        int slot = g_off[e] + p;
        g_pairtok[slot] = t;
        g_slotof[2 * t + k] = slot;
    }
}

// ---------------- rmsnorm over rows of length DMODEL (256 thr, float4) ----------------
__global__ void rmsnorm_rows(const float* __restrict__ X,
                             const float* __restrict__ w,
                             float* __restrict__ Y)
{
    int row = blockIdx.x;
    int tid = threadIdx.x;                       // 256
    const float4* xr = (const float4*)(X + (long long)row * DMODEL);
    float4 v = xr[tid];
    float ss = v.x * v.x + v.y * v.y + v.z * v.z + v.w * v.w;
    __shared__ float red[8];
    #pragma unroll
    for (int o = 16; o; o >>= 1) ss += __shfl_xor_sync(0xffffffffu, ss, o);
    if ((tid & 31) == 0) red[tid >> 5] = ss;
    __syncthreads();
    float tot = red[0] + red[1] + red[2] + red[3] + red[4] + red[5] + red[6] + red[7];
    float r = rsqrtf(tot * (1.0f / DMODEL) + EPSF);
    float4 wv = ((const float4*)w)[tid];
    float4 o4;
    o4.x = v.x * r * wv.x; o4.y = v.y * r * wv.y;
    o4.z = v.z * r * wv.z; o4.w = v.w * r * wv.w;
    ((float4*)(Y + (long long)row * DMODEL))[tid] = o4;
}

// ---------------- router: one warp per token ----------------
__global__ void router_kernel(const float* __restrict__ h,
                              const float* __restrict__ Wr,
                              const float* __restrict__ bias)
{
    int warp = (blockIdx.x * blockDim.x + threadIdx.x) >> 5;
    int lane = threadIdx.x & 31;
    if (warp >= N_TOK) return;
    const float* hr = h + (long long)warp * DMODEL;
    float acc[NEXP];
    #pragma unroll
    for (int e = 0; e < NEXP; e++) acc[e] = 0.0f;
    for (int d = lane; d < DMODEL; d += 32) {
        float hv = hr[d];
        #pragma unroll
        for (int e = 0; e < NEXP; e++) acc[e] += hv * Wr[e * DMODEL + d];
    }
    #pragma unroll
    for (int e = 0; e < NEXP; e++) {
        #pragma unroll
        for (int o = 16; o; o >>= 1) acc[e] += __shfl_xor_sync(0xffffffffu, acc[e], o);
    }
    if (lane == 0) {
        float b0 = -1e30f, b1 = -1e30f; int i0 = 0, i1 = 0;
        #pragma unroll
        for (int e = 0; e < NEXP; e++) {
            float v = acc[e] + bias[e];
            if (v > b0) { b1 = b0; i1 = i0; b0 = v; i0 = e; }
            else if (v > b1) { b1 = v; i1 = e; }
        }
        float l0 = acc[i0], l1 = acc[i1];
        float m = fmaxf(l0, l1);
        float e0 = expf(l0 - m), e1 = expf(l1 - m);
        float inv = 1.0f / (e0 + e1);
        g_topidx[2 * warp] = i0;  g_topidx[2 * warp + 1] = i1;
        g_topgate[2 * warp] = e0 * inv; g_topgate[2 * warp + 1] = e1 * inv;
        atomicAdd(&g_cnt[i0], 1);
        atomicAdd(&g_cnt[i1], 1);
    }
}

// ---------------- generic SGEMM: C[M,N] = A[M,K] * B[N,K]^T ----------------
// 128x128 tile, BK=8, 256 threads, 8x8 per thread, smem double-buffered.
// GROUPED=1: blockIdx.z = expert, rows come from d_off[e]..d_off[e+1].
template<int GROUPED>
__global__ __launch_bounds__(256) void gemm128_nt(
    const float* __restrict__ A, const float* __restrict__ B, float* __restrict__ C,
    int M, int Ncols, int Kdim,
    const int* __restrict__ gather, const int* __restrict__ d_off, long long strideB)
{
    int rowBase = 0, Mloc = M;
    const float* Bp = B;
    if (GROUPED) {
        int e = blockIdx.z;
        rowBase = d_off[e];
        Mloc = d_off[e + 1] - rowBase;
        Bp = B + (long long)e * strideB;
    }
    int bm = blockIdx.x * 128;
    if (bm >= Mloc) return;
    int bn = blockIdx.y * 128;

    __shared__ __align__(16) float As[2][8][128];
    __shared__ __align__(16) float Bs[2][8][128];

    int tid = threadIdx.x;
    int tx = tid & 15;
    int ty = tid >> 4;
    int lr = tid >> 1;
    int lc = (tid & 1) * 4;

    int arl = bm + lr; if (arl >= Mloc) arl = Mloc - 1;
    int gidx = rowBase + arl;
    long long arow = gather ? (long long)gather[gidx] : (long long)gidx;
    const float* Arow = A + arow * Kdim + lc;
    const float* Brow = Bp + (long long)(bn + lr) * Kdim + lc;

    float acc[8][8];
    #pragma unroll
    for (int i = 0; i < 8; i++)
        #pragma unroll
        for (int j = 0; j < 8; j++) acc[i][j] = 0.0f;

    int ntiles = Kdim >> 3;
    float4 ra = *(const float4*)(Arow);
    float4 rb = *(const float4*)(Brow);
    As[0][lc + 0][lr] = ra.x; As[0][lc + 1][lr] = ra.y;
    As[0][lc + 2][lr] = ra.z; As[0][lc + 3][lr] = ra.w;
    Bs[0][lc + 0][lr] = rb.x; Bs[0][lc + 1][lr] = rb.y;
    Bs[0][lc + 2][lr] = rb.z; Bs[0][lc + 3][lr] = rb.w;

    for (int kt = 0; kt < ntiles; kt++) {
        __syncthreads();
        int buf = kt & 1;
        bool more = (kt + 1) < ntiles;
        if (more) {
            ra = *(const float4*)(Arow + (kt + 1) * 8);
            rb = *(const float4*)(Brow + (kt + 1) * 8);
        }
        #pragma unroll
        for (int kk = 0; kk < 8; kk++) {
            float4 a0 = *(const float4*)&As[buf][kk][ty * 8];
            float4 a1 = *(const float4*)&As[buf][kk][ty * 8 + 4];
            float4 b0 = *(const float4*)&Bs[buf][kk][tx * 8];
            float4 b1 = *(const float4*)&Bs[buf][kk][tx * 8 + 4];
            float av[8] = {a0.x, a0.y, a0.z, a0.w, a1.x, a1.y, a1.z, a1.w};
            float bv[8] = {b0.x, b0.y, b0.z, b0.w, b1.x, b1.y, b1.z, b1.w};
            #pragma unroll
            for (int i = 0; i < 8; i++)
                #pragma unroll
                for (int j = 0; j < 8; j++) acc[i][j] += av[i] * bv[j];
        }
        if (more) {
            int nb = buf ^ 1;
            As[nb][lc + 0][lr] = ra.x; As[nb][lc + 1][lr] = ra.y;
            As[nb][lc + 2][lr] = ra.z; As[nb][lc + 3][lr] = ra.w;
            Bs[nb][lc + 0][lr] = rb.x; Bs[nb][lc + 1][lr] = rb.y;
            Bs[nb][lc + 2][lr] = rb.z; Bs[nb][lc + 3][lr] = rb.w;
        }
    }

    #pragma unroll
    for (int i = 0; i < 8; i++) {
        int r = bm + ty * 8 + i;
        if (r < Mloc) {
            float* Crow = C + (long long)(rowBase + r) * Ncols + bn + tx * 8;
            float4 c0 = make_float4(acc[i][0], acc[i][1], acc[i][2], acc[i][3]);
            float4 c1 = make_float4(acc[i][4], acc[i][5], acc[i][6], acc[i][7]);
            *(float4*)(Crow) = c0;
            *(float4*)(Crow + 4) = c1;
        }
    }
}

// ---------------- fused gate/up GEMM: T[slot,f] = silu(h.Wg[e][f]) * (h.Wu[e][f]) ----------------
// 128x64 tile, BK=8, 256 threads, per-thread 8x4 for each of the two accumulators.
__global__ __launch_bounds__(256) void gemm_gateup(
    const float* __restrict__ H, const float* __restrict__ Wg,
    const float* __restrict__ Wu, float* __restrict__ T,
    const int* __restrict__ pairtok, const int* __restrict__ d_off)
{
    int e = blockIdx.z;
    int rowBase = d_off[e];
    int Mloc = d_off[e + 1] - rowBase;
    int bm = blockIdx.x * 128;
    if (bm >= Mloc) return;
    int bn = blockIdx.y * 64;

    const float* Bg = Wg + (long long)e * DFF * DMODEL;
    const float* Bu = Wu + (long long)e * DFF * DMODEL;

    __shared__ __align__(16) float As[2][8][128];
    __shared__ __align__(16) float Gs[2][8][64];
    __shared__ __align__(16) float Us[2][8][64];

    int tid = threadIdx.x;
    int tx = tid & 15;   // cols tx*4 .. tx*4+3
    int ty = tid >> 4;   // rows ty*8 ..
    int lr = tid >> 1;
    int lc = (tid & 1) * 4;

    int arl = bm + lr; if (arl >= Mloc) arl = Mloc - 1;
    int tok = pairtok[rowBase + arl];
    const float* Arow = H + (long long)tok * DMODEL + lc;

    int grp = tid >> 7;          // 0 -> Wg, 1 -> Wu
    int t2 = tid & 127;
    int br = t2 >> 1;            // 0..63
    int bc = (t2 & 1) * 4;
    const float* Brow = (grp ? Bu : Bg) + (long long)(bn + br) * DMODEL + bc;

    float accg[8][4], accu[8][4];
    #pragma unroll
    for (int i = 0; i < 8; i++)
        #pragma unroll
        for (int j = 0; j < 4; j++) { accg[i][j] = 0.0f; accu[i][j] = 0.0f; }

    int ntiles = DMODEL >> 3;
    float4 ra = *(const float4*)(Arow);
    float4 rb = *(const float4*)(Brow);
    As[0][lc + 0][lr] = ra.x; As[0][lc + 1][lr] = ra.y;
    As[0][lc + 2][lr] = ra.z; As[0][lc + 3][lr] = ra.w;
    if (grp == 0) {
        Gs[0][bc + 0][br] = rb.x; Gs[0][bc + 1][br] = rb.y;
        Gs[0][bc + 2][br] = rb.z; Gs[0][bc + 3][br] = rb.w;
    } else {
        Us[0][bc + 0][br] = rb.x; Us[0][bc + 1][br] = rb.y;
        Us[0][bc + 2][br] = rb.z; Us[0][bc + 3][br] = rb.w;
    }

    for (int kt = 0; kt < ntiles; kt++) {
        __syncthreads();
        int buf = kt & 1;
        bool more = (kt + 1) < ntiles;
        if (more) {
            ra = *(const float4*)(Arow + (kt + 1) * 8);
            rb = *(const float4*)(Brow + (kt + 1) * 8);
        }
        #pragma unroll
        for (int kk = 0; kk < 8; kk++) {
            float4 a0 = *(const float4*)&As[buf][kk][ty * 8];
            float4 a1 = *(const float4*)&As[buf][kk][ty * 8 + 4];
            float4 gg = *(const float4*)&Gs[buf][kk][tx * 4];
            float4 uu = *(const float4*)&Us[buf][kk][tx * 4];
            float av[8] = {a0.x, a0.y, a0.z, a0.w, a1.x, a1.y, a1.z, a1.w};
            float gv[4] = {gg.x, gg.y, gg.z, gg.w};
            float uv[4] = {uu.x, uu.y, uu.z, uu.w};
            #pragma unroll
            for (int i = 0; i < 8; i++)
                #pragma unroll
                for (int j = 0; j < 4; j++) {
                    accg[i][j] += av[i] * gv[j];
                    accu[i][j] += av[i] * uv[j];
                }
        }
        if (more) {
            int nb = buf ^ 1;
            As[nb][lc + 0][lr] = ra.x; As[nb][lc + 1][lr] = ra.y;
            As[nb][lc + 2][lr] = ra.z; As[nb][lc + 3][lr] = ra.w;
            if (grp == 0) {
                Gs[nb][bc + 0][br] = rb.x; Gs[nb][bc + 1][br] = rb.y;
                Gs[nb][bc + 2][br] = rb.z; Gs[nb][bc + 3][br] = rb.w;
            } else {
                Us[nb][bc + 0][br] = rb.x; Us[nb][bc + 1][br] = rb.y;
                Us[nb][bc + 2][br] = rb.z; Us[nb][bc + 3][br] = rb.w;
            }
        }
    }

    #pragma unroll
    for (int i = 0; i < 8; i++) {
        int r = bm + ty * 8 + i;
        if (r < Mloc) {
            float* Trow = T + (long long)(rowBase + r) * DFF + bn + tx * 4;
            float4 o4;
            float g0, u0;
            g0 = accg[i][0]; u0 = accu[i][0]; o4.x = (g0 / (1.0f + __expf(-g0))) * u0;
            g0 = accg[i][1]; u0 = accu[i][1]; o4.y = (g0 / (1.0f + __expf(-g0))) * u0;
            g0 = accg[i][2]; u0 = accu[i][2]; o4.z = (g0 / (1.0f + __expf(-g0))) * u0;
            g0 = accg[i][3]; u0 = accu[i][3]; o4.w = (g0 / (1.0f + __expf(-g0))) * u0;
            *(float4*)Trow = o4;
        }
    }
}

// ---------------- combine: per-token expert-rmsnorm, gate-weighted sum, out-rmsnorm ----------------
__global__ void combine_rows(const float* __restrict__ enorm,
                             const float* __restrict__ outnorm)
{
    int t = blockIdx.x;
    int tid = threadIdx.x;   // 256
    int s0 = g_slotof[2 * t], s1 = g_slotof[2 * t + 1];
    int e0 = g_topidx[2 * t], e1 = g_topidx[2 * t + 1];
    float gg0 = g_topgate[2 * t], gg1 = g_topgate[2 * t + 1];

    float4 a = ((const float4*)(g_Oe + (long long)s0 * DMODEL))[tid];
    float4 b = ((const float4*)(g_Oe + (long long)s1 * DMODEL))[tid];
    float ssa = a.x * a.x + a.y * a.y + a.z * a.z + a.w * a.w;
    float ssb = b.x * b.x + b.y * b.y + b.z * b.z + b.w * b.w;

    __shared__ float redA[8], redB[8], redC[8];
    #pragma unroll
    for (int o = 16; o; o >>= 1) {
        ssa += __shfl_xor_sync(0xffffffffu, ssa, o);
        ssb += __shfl_xor_sync(0xffffffffu, ssb, o);
    }
    if ((tid & 31) == 0) { redA[tid >> 5] = ssa; redB[tid >> 5] = ssb; }
    __syncthreads();
    float ta = redA[0] + redA[1] + redA[2] + redA[3] + redA[4] + redA[5] + redA[6] + redA[7];
    float tb = redB[0] + redB[1] + redB[2] + redB[3] + redB[4] + redB[5] + redB[6] + redB[7];
    float r0 = rsqrtf(ta * (1.0f / DMODEL) + EPSF) * gg0;
    float r1 = rsqrtf(tb * (1.0f / DMODEL) + EPSF) * gg1;

    float4 w0 = ((const float4*)(enorm + (long long)e0 * DMODEL))[tid];
    float4 w1 = ((const float4*)(enorm + (long long)e1 * DMODEL))[tid];
    float4 c;
    c.x = a.x * r0 * w0.x + b.x * r1 * w1.x;
    c.y = a.y * r0 * w0.y + b.y * r1 * w1.y;
    c.z = a.z * r0 * w0.z + b.z * r1 * w1.z;
    c.w = a.w * r0 * w0.w + b.w * r1 * w1.w;

    float ssc = c.x * c.x + c.y * c.y + c.z * c.z + c.w * c.w;
    #pragma unroll
    for (int o = 16; o; o >>= 1) ssc += __shfl_xor_sync(0xffffffffu, ssc, o);
    if ((tid & 31) == 0) redC[tid >> 5] = ssc;
    __syncthreads();
    float tc = redC[0] + redC[1] + redC[2] + redC[3] + redC[4] + redC[5] + redC[6] + redC[7];
    float rc = rsqrtf(tc * (1.0f / DMODEL) + EPSF);

    float4 wo = ((const float4*)outnorm)[tid];
    float4 o4;
    o4.x = c.x * rc * wo.x; o4.y = c.y * rc * wo.y;
    o4.z = c.z * rc * wo.z; o4.w = c.w * rc * wo.w;
    ((float4*)(g_y + (long long)t * DMODEL))[tid] = o4;
}

// ---------------- launch ----------------
extern "C" void kernel_launch(void* const* d_in, const int* in_sizes, int n_in,
                              void* d_out, int out_size)
{
    const float* s          = (const float*)d_in[0];
    const float* W_in       = (const float*)d_in[1];
    const float* in_norm_w  = (const float*)d_in[2];
    const float* Wr         = (const float*)d_in[3];
    const float* expert_bias= (const float*)d_in[4];
    const float* Wg         = (const float*)d_in[5];
    const float* Wu         = (const float*)d_in[6];
    const float* Wd         = (const float*)d_in[7];
    const float* enorm_w    = (const float*)d_in[8];
    const float* out_norm_w = (const float*)d_in[9];
    const float* W_out      = (const float*)d_in[10];
    float* out = (float*)d_out;

    void *p_h, *p_y, *p_T, *p_Oe, *p_off, *p_pairtok;
    cudaGetSymbolAddress(&p_h, g_h);
    cudaGetSymbolAddress(&p_y, g_y);
    cudaGetSymbolAddress(&p_T, g_T);
    cudaGetSymbolAddress(&p_Oe, g_Oe);
    cudaGetSymbolAddress(&p_off, g_off);
    cudaGetSymbolAddress(&p_pairtok, g_pairtok);
    float* h_ptr  = (float*)p_h;
    float* y_ptr  = (float*)p_y;
    float* T_ptr  = (float*)p_T;
    float* Oe_ptr = (float*)p_Oe;
    int* off_ptr  = (int*)p_off;
    int* ptok_ptr = (int*)p_pairtok;

    init_counts<<<1, 32>>>();

    // h_pre = s @ W_in^T
    gemm128_nt<0><<<dim3(N_TOK / 128, DMODEL / 128, 1), 256>>>(
        s, W_in, h_ptr, N_TOK, DMODEL, DMODEL, nullptr, nullptr, 0);

    // h = rmsnorm(h_pre) (in place)
    rmsnorm_rows<<<N_TOK, 256>>>(h_ptr, in_norm_w, h_ptr);

    // router + top-2 + counts
    router_kernel<<<(N_TOK * 32) / 256, 256>>>(h_ptr, Wr, expert_bias);

    scan_offsets<<<1, 32>>>();
    scatter_pairs<<<N_TOK / 256, 256>>>();

    // T = silu(h Wg^T) * (h Wu^T), grouped by expert
    gemm_gateup<<<dim3(NPAIR / 128, DFF / 64, NEXP), 256>>>(
        h_ptr, Wg, Wu, T_ptr, ptok_ptr, off_ptr);

    // Oe = T @ Wd[e]^T, grouped by expert
    gemm128_nt<1><<<dim3(NPAIR / 128, DMODEL / 128, NEXP), 256>>>(
        T_ptr, Wd, Oe_ptr, 0, DMODEL, DFF, nullptr, off_ptr,
        (long long)DMODEL * DFF);

    // per-token combine (expert rmsnorm + gates + output rmsnorm) -> g_y
    combine_rows<<<N_TOK, 256>>>(enorm_w, out_norm_w);

    // s_hat = y @ W_out^T
    gemm128_nt<0><<<dim3(N_TOK / 128, DMODEL / 128, 1), 256>>>(
        y_ptr, W_out, out, N_TOK, DMODEL, DMODEL, nullptr, nullptr, 0);
}

// round 4
// speedup vs baseline: 2.6863x; 2.6829x over previous
#include <cuda_runtime.h>
#include <cuda_bf16.h>

#define N_TOK 8192
#define DMODEL 1024
#define DFF 4096
#define NEXP 8
#define NPAIR (N_TOK * 2)
#define EPSF 1.1920928955078125e-07f
#define STAGE 65536u
#define SMEM_DYN (2 * 65536)
typedef __nv_bfloat16 bf;
typedef __nv_bfloat162 bf2;
typedef long long ll;

__device__ float g_h[(size_t)N_TOK * DMODEL];
__device__ float g_Oe[(size_t)NPAIR * DMODEL];
__device__ bf g_sH[(size_t)N_TOK*DMODEL], g_sL[(size_t)N_TOK*DMODEL];
__device__ bf g_hH[(size_t)N_TOK*DMODEL], g_hL[(size_t)N_TOK*DMODEL];
__device__ bf g_yH[(size_t)N_TOK*DMODEL], g_yL[(size_t)N_TOK*DMODEL];
__device__ bf g_TH[(size_t)NPAIR*DFF], g_TL[(size_t)NPAIR*DFF];
__device__ bf g_WinH[(size_t)DMODEL*DMODEL], g_WinL[(size_t)DMODEL*DMODEL];
__device__ bf g_WgH[(size_t)NEXP*DFF*DMODEL], g_WgL[(size_t)NEXP*DFF*DMODEL];
__device__ bf g_WuH[(size_t)NEXP*DFF*DMODEL], g_WuL[(size_t)NEXP*DFF*DMODEL];
__device__ bf g_WdH[(size_t)NEXP*DMODEL*DFF], g_WdL[(size_t)NEXP*DMODEL*DFF];
__device__ bf g_WoH[(size_t)DMODEL*DMODEL], g_WoL[(size_t)DMODEL*DMODEL];
__device__ int g_cnt[NEXP], g_off[NEXP+1], g_cur[NEXP];
__device__ int g_pairtok[NPAIR], g_slotof[NPAIR], g_topidx[NPAIR];
__device__ float g_topgate[NPAIR];

__device__ __forceinline__ unsigned su32(const void* p){
    unsigned a; asm("{ .reg .u64 t; cvta.to.shared.u64 t, %1; cvt.u32.u64 %0, t; }":"=r"(a):"l"(p)); return a;
}
__device__ __forceinline__ void cp16(unsigned d, const void* s){
    asm volatile("cp.async.cg.shared.global [%0], [%1], 16;"::"r"(d),"l"(s));
}
__device__ __forceinline__ unsigned swz(unsigned off){ return off ^ ((off>>3)&0x70u); }
__device__ __forceinline__ void ldsm4(unsigned* r, unsigned a){
    asm volatile("ldmatrix.sync.aligned.m8n8.x4.shared.b16 {%0,%1,%2,%3}, [%4];"
        :"=r"(r[0]),"=r"(r[1]),"=r"(r[2]),"=r"(r[3]):"r"(a));
}
__device__ __forceinline__ void ldsm2(unsigned* r, unsigned a){
    asm volatile("ldmatrix.sync.aligned.m8n8.x2.shared.b16 {%0,%1}, [%2];"
        :"=r"(r[0]),"=r"(r[1]):"r"(a));
}
__device__ __forceinline__ void mma16816(float* c, const unsigned* a, const unsigned* b){
    asm volatile("mma.sync.aligned.m16n8k16.row.col.f32.bf16.bf16.f32 "
        "{%0,%1,%2,%3},{%4,%5,%6,%7},{%8,%9},{%0,%1,%2,%3};"
        :"+f"(c[0]),"+f"(c[1]),"+f"(c[2]),"+f"(c[3])
        :"r"(a[0]),"r"(a[1]),"r"(a[2]),"r"(a[3]),"r"(b[0]),"r"(b[1]));
}
__device__ __forceinline__ void split2(float x, bf& h, bf& l){
    h = __float2bfloat16(x); l = __float2bfloat16(x - __bfloat162float(h));
}

__global__ void init_counts(){ if (threadIdx.x < NEXP) g_cnt[threadIdx.x] = 0; }
__global__ void scan_offsets(){
    if (threadIdx.x == 0){ int s=0; for(int e=0;e<NEXP;e++){ g_off[e]=s; s+=g_cnt[e]; } g_off[NEXP]=s; }
    if (threadIdx.x < NEXP) g_cur[threadIdx.x] = 0;
}
__global__ void scatter_pairs(){
    int t = blockIdx.x*blockDim.x + threadIdx.x; if (t >= N_TOK) return;
    for (int k=0;k<2;k++){
        int e = g_topidx[2*t+k];
        int slot = g_off[e] + atomicAdd(&g_cur[e],1);
        g_pairtok[slot] = t; g_slotof[2*t+k] = slot;
    }
}
__global__ void convert_hilo(const float* __restrict__ x, bf* __restrict__ h, bf* __restrict__ l, int n4){
    int i = blockIdx.x*blockDim.x + threadIdx.x; if (i >= n4) return;
    float4 v = ((const float4*)x)[i];
    bf2 p0,p1,q0,q1;
    split2(v.x,p0.x,q0.x); split2(v.y,p0.y,q0.y); split2(v.z,p1.x,q1.x); split2(v.w,p1.y,q1.y);
    ((bf2*)h)[2*i]=p0; ((bf2*)h)[2*i+1]=p1; ((bf2*)l)[2*i]=q0; ((bf2*)l)[2*i+1]=q1;
}
__global__ void rmsnorm_hilo(const float* __restrict__ X, const float* __restrict__ w,
                             float* __restrict__ Y, bf* __restrict__ YH, bf* __restrict__ YL){
    int row = blockIdx.x, tid = threadIdx.x;
    float4 v = ((const float4*)(X + (ll)row*DMODEL))[tid];
    float ss = v.x*v.x+v.y*v.y+v.z*v.z+v.w*v.w;
    __shared__ float red[8];
    for (int o=16;o;o>>=1) ss += __shfl_xor_sync(~0u, ss, o);
    if ((tid&31)==0) red[tid>>5]=ss;
    __syncthreads();
    float tot = red[0]+red[1]+red[2]+red[3]+red[4]+red[5]+red[6]+red[7];
    float r = rsqrtf(tot*(1.0f/DMODEL)+EPSF);
    float4 wv = ((const float4*)w)[tid];
    float4 o4 = make_float4(v.x*r*wv.x, v.y*r*wv.y, v.z*r*wv.z, v.w*r*wv.w);
    if (Y) ((float4*)(Y + (ll)row*DMODEL))[tid] = o4;
    bf2 p0,p1,q0,q1;
    split2(o4.x,p0.x,q0.x); split2(o4.y,p0.y,q0.y); split2(o4.z,p1.x,q1.x); split2(o4.w,p1.y,q1.y);
    bf2* ph=(bf2*)(YH+(ll)row*DMODEL); bf2* pl=(bf2*)(YL+(ll)row*DMODEL);
    ph[2*tid]=p0; ph[2*tid+1]=p1; pl[2*tid]=q0; pl[2*tid+1]=q1;
}
__global__ void router_kernel(const float* __restrict__ h, const float* __restrict__ Wr, const float* __restrict__ bias){
    int warp = (blockIdx.x*blockDim.x+threadIdx.x)>>5, lane = threadIdx.x&31;
    if (warp >= N_TOK) return;
    const float* hr = h + (ll)warp*DMODEL;
    float acc[NEXP];
    #pragma unroll
    for (int e=0;e<NEXP;e++) acc[e]=0.f;
    for (int d=lane; d<DMODEL; d+=32){
        float hv = hr[d];
        #pragma unroll
        for (int e=0;e<NEXP;e++) acc[e] += hv*Wr[e*DMODEL+d];
    }
    #pragma unroll
    for (int e=0;e<NEXP;e++)
        for (int o=16;o;o>>=1) acc[e] += __shfl_xor_sync(~0u, acc[e], o);
    if (lane==0){
        float b0=-1e30f,b1=-1e30f; int i0=0,i1=0;
        #pragma unroll
        for (int e=0;e<NEXP;e++){
            float v = acc[e]+bias[e];
            if (v>b0){ b1=b0;i1=i0;b0=v;i0=e; } else if (v>b1){ b1=v;i1=e; }
        }
        float m=fmaxf(acc[i0],acc[i1]);
        float e0=expf(acc[i0]-m), e1=expf(acc[i1]-m), inv=1.f/(e0+e1);
        g_topidx[2*warp]=i0; g_topidx[2*warp+1]=i1;
        g_topgate[2*warp]=e0*inv; g_topgate[2*warp+1]=e1*inv;
        atomicAdd(&g_cnt[i0],1); atomicAdd(&g_cnt[i1],1);
    }
}

// split-bf16 HMMA GEMM: C = A*B^T via Ah.Bh + Ah.Bl + Al.Bh (fp32 accum).
// Block tile 128 x (DUAL? 2x64 : 128), BK=64, 2-stage cp.async, 256 thr / 8 warps.
template<int DUAL, int GROUPED, int GATHER>
__global__ __launch_bounds__(256) void mm_kernel(
    const bf* __restrict__ Ah, const bf* __restrict__ Al,
    const bf* __restrict__ B0h, const bf* __restrict__ B0l,
    const bf* __restrict__ B1h, const bf* __restrict__ B1l,
    float* __restrict__ C, bf* __restrict__ TH, bf* __restrict__ TL,
    int Mdense, int K, int Ncols,
    const int* __restrict__ d_off, const int* __restrict__ pairtok, ll strideB)
{
    extern __shared__ char dsm[];
    constexpr int BN = DUAL ? 64 : 128;
    constexpr int MT = DUAL ? 2 : 4;
    constexpr unsigned BLO = DUAL ? 8192u : 16384u;   // hi/lo gap inside B block
    int rowBase = 0, Mloc = Mdense;
    const bf *b0h=B0h,*b0l=B0l,*b1h=B1h,*b1l=B1l;
    if (GROUPED){
        int e = blockIdx.z;
        rowBase = d_off[e]; Mloc = d_off[e+1]-rowBase;
        b0h += (ll)e*strideB; b0l += (ll)e*strideB;
        if (DUAL){ b1h += (ll)e*strideB; b1l += (ll)e*strideB; }
    }
    int bm = blockIdx.x*128; if (bm >= Mloc) return;
    int bn = blockIdx.y*BN;

    unsigned sb = su32(dsm);
    int tid = threadIdx.x;
    int aslot = tid&7, arow0 = tid>>3;   // slot = 16B chunk within 128B row

    // A row gather (4 rows per thread, fixed across stages)
    ll ga[4];
    #pragma unroll
    for (int j=0;j<4;j++){
        int lr = bm + arow0 + 32*j; if (lr > Mloc-1) lr = Mloc-1;
        if (GATHER) ga[j] = pairtok[rowBase+lr];
        else if (GROUPED) ga[j] = rowBase+lr;
        else ga[j] = lr;
    }

    int w = tid>>5, lane = tid&31;
    int wm = DUAL ? (w>>1)*32 : (w>>2)*64;
    int wn = DUAL ? (w&1)*32  : (w&3)*32;

    float acc[4][4][4];
    #pragma unroll
    for (int i=0;i<4;i++)
        #pragma unroll
        for (int j=0;j<4;j++)
            #pragma unroll
            for (int q=0;q<4;q++) acc[i][j][q] = 0.f;

    int total = K>>6;
    for (int c = -1; c < total; ++c){
        int nl = c+1;
        if (nl < total){
            unsigned base = sb + (unsigned)(nl&1)*STAGE;
            int ke = nl*64 + aslot*8;
            #pragma unroll
            for (int j=0;j<4;j++){
                unsigned sw = swz((unsigned)((arow0+32*j)*128 + aslot*16));
                cp16(base+sw,        Ah + ga[j]*K + ke);
                cp16(base+16384u+sw, Al + ga[j]*K + ke);
            }
            if (!DUAL){
                #pragma unroll
                for (int j=0;j<4;j++){
                    int br = bn + arow0 + 32*j;
                    unsigned sw = swz((unsigned)((arow0+32*j)*128 + aslot*16));
                    cp16(base+32768u+sw, b0h + (ll)br*K + ke);
                    cp16(base+49152u+sw, b0l + (ll)br*K + ke);
                }
            } else {
                #pragma unroll
                for (int j=0;j<2;j++){
                    int r = arow0 + 32*j;       // 0..63
                    int br = bn + r;
                    unsigned sw = swz((unsigned)(r*128 + aslot*16));
                    cp16(base+32768u+sw, b0h + (ll)br*K + ke);
                    cp16(base+40960u+sw, b0l + (ll)br*K + ke);
                    cp16(base+49152u+sw, b1h + (ll)br*K + ke);
                    cp16(base+57344u+sw, b1l + (ll)br*K + ke);
                }
            }
            asm volatile("cp.async.commit_group;":::"memory");
        }
        if (c < 0) continue;
        if (nl < total) asm volatile("cp.async.wait_group 1;":::"memory");
        else            asm volatile("cp.async.wait_group 0;":::"memory");
        __syncthreads();

        unsigned base = sb + (unsigned)(c&1)*STAGE;
        int mat = lane>>3, r8 = lane&7;
        #pragma unroll
        for (int s=0;s<4;s++){
            unsigned ah[4][4], al[4][4], bh[4][2], blo[4][2], buh[4][2], bul[4][2];
            int kbA = s*32 + (mat>>1)*16;
            #pragma unroll
            for (int tm=0;tm<MT;tm++){
                int row = wm + tm*16 + (mat&1)*8 + r8;
                unsigned sw = swz((unsigned)(row*128 + kbA));
                ldsm4(ah[tm], base + sw);
                ldsm4(al[tm], base + 16384u + sw);
            }
            int kbB = s*32 + ((lane>>3)&1)*16;
            #pragma unroll
            for (int tn=0;tn<4;tn++){
                int row = wn + tn*8 + (lane&7);
                unsigned sw = swz((unsigned)(row*128 + kbB));
                ldsm2(bh[tn],  base + 32768u + sw);
                ldsm2(blo[tn], base + 32768u + BLO + sw);
                if (DUAL){
                    ldsm2(buh[tn], base + 49152u + sw);
                    ldsm2(bul[tn], base + 57344u + sw);
                }
            }
            #pragma unroll
            for (int tm=0;tm<MT;tm++)
                #pragma unroll
                for (int tn=0;tn<4;tn++){
                    mma16816(acc[tm][tn], ah[tm], bh[tn]);
                    mma16816(acc[tm][tn], ah[tm], blo[tn]);
                    mma16816(acc[tm][tn], al[tm], bh[tn]);
                    if (DUAL){
                        mma16816(acc[2+tm][tn], ah[tm], buh[tn]);
                        mma16816(acc[2+tm][tn], ah[tm], bul[tn]);
                        mma16816(acc[2+tm][tn], al[tm], buh[tn]);
                    }
                }
        }
        __syncthreads();
    }

    int rl = wm + (lane>>2);
    int coff = wn + (lane&3)*2;
    if (!DUAL){
        #pragma unroll
        for (int tm=0;tm<4;tm++)
            #pragma unroll
            for (int tn=0;tn<4;tn++){
                float* cc = acc[tm][tn];
                int r = bm + rl + tm*16;
                int col = bn + coff + tn*8;
                if (r < Mloc)
                    *(float2*)(C + (ll)(rowBase+r)*Ncols + col) = make_float2(cc[0],cc[1]);
                if (r+8 < Mloc)
                    *(float2*)(C + (ll)(rowBase+r+8)*Ncols + col) = make_float2(cc[2],cc[3]);
            }
    } else {
        #pragma unroll
        for (int tm=0;tm<2;tm++)
            #pragma unroll
            for (int tn=0;tn<4;tn++){
                float* gg = acc[tm][tn];
                float* uu = acc[2+tm][tn];
                float v0 = gg[0]*uu[0]/(1.f+__expf(-gg[0]));
                float v1 = gg[1]*uu[1]/(1.f+__expf(-gg[1]));
                float v2 = gg[2]*uu[2]/(1.f+__expf(-gg[2]));
                float v3 = gg[3]*uu[3]/(1.f+__expf(-gg[3]));
                int r = bm + rl + tm*16;
                int col = bn + coff + tn*8;
                bf2 h0,l0,h1,l1;
                split2(v0,h0.x,l0.x); split2(v1,h0.y,l0.y);
                split2(v2,h1.x,l1.x); split2(v3,h1.y,l1.y);
                if (r < Mloc){
                    *(bf2*)(TH + (ll)(rowBase+r)*Ncols + col) = h0;
                    *(bf2*)(TL + (ll)(rowBase+r)*Ncols + col) = l0;
                }
                if (r+8 < Mloc){
                    *(bf2*)(TH + (ll)(rowBase+r+8)*Ncols + col) = h1;
                    *(bf2*)(TL + (ll)(rowBase+r+8)*Ncols + col) = l1;
                }
            }
    }
}

__global__ void combine_rows(const float* __restrict__ enorm, const float* __restrict__ outnorm){
    int t = blockIdx.x, tid = threadIdx.x;
    int s0=g_slotof[2*t], s1=g_slotof[2*t+1], e0=g_topidx[2*t], e1=g_topidx[2*t+1];
    float gg0=g_topgate[2*t], gg1=g_topgate[2*t+1];
    float4 a = ((const float4*)(g_Oe+(ll)s0*DMODEL))[tid];
    float4 b = ((const float4*)(g_Oe+(ll)s1*DMODEL))[tid];
    float ssa=a.x*a.x+a.y*a.y+a.z*a.z+a.w*a.w, ssb=b.x*b.x+b.y*b.y+b.z*b.z+b.w*b.w;
    __shared__ float rA[8],rB[8],rC[8];
    for (int o=16;o;o>>=1){ ssa+=__shfl_xor_sync(~0u,ssa,o); ssb+=__shfl_xor_sync(~0u,ssb,o); }
    if ((tid&31)==0){ rA[tid>>5]=ssa; rB[tid>>5]=ssb; }
    __syncthreads();
    float ta=rA[0]+rA[1]+rA[2]+rA[3]+rA[4]+rA[5]+rA[6]+rA[7];
    float tb=rB[0]+rB[1]+rB[2]+rB[3]+rB[4]+rB[5]+rB[6]+rB[7];
    float r0=rsqrtf(ta*(1.f/DMODEL)+EPSF)*gg0, r1=rsqrtf(tb*(1.f/DMODEL)+EPSF)*gg1;
    float4 w0=((const float4*)(enorm+(ll)e0*DMODEL))[tid];
    float4 w1=((const float4*)(enorm+(ll)e1*DMODEL))[tid];
    float4 c = make_float4(a.x*r0*w0.x+b.x*r1*w1.x, a.y*r0*w0.y+b.y*r1*w1.y,
                           a.z*r0*w0.z+b.z*r1*w1.z, a.w*r0*w0.w+b.w*r1*w1.w);
    float ssc=c.x*c.x+c.y*c.y+c.z*c.z+c.w*c.w;
    for (int o=16;o;o>>=1) ssc+=__shfl_xor_sync(~0u,ssc,o);
    if ((tid&31)==0) rC[tid>>5]=ssc;
    __syncthreads();
    float tc=rC[0]+rC[1]+rC[2]+rC[3]+rC[4]+rC[5]+rC[6]+rC[7];
    float rc=rsqrtf(tc*(1.f/DMODEL)+EPSF);
    float4 wo=((const float4*)outnorm)[tid];
    float4 o4=make_float4(c.x*rc*wo.x, c.y*rc*wo.y, c.z*rc*wo.z, c.w*rc*wo.w);
    bf2 p0,p1,q0,q1;
    split2(o4.x,p0.x,q0.x); split2(o4.y,p0.y,q0.y); split2(o4.z,p1.x,q1.x); split2(o4.w,p1.y,q1.y);
    bf2* ph=(bf2*)(g_yH+(ll)t*DMODEL); bf2* pl=(bf2*)(g_yL+(ll)t*DMODEL);
    ph[2*tid]=p0; ph[2*tid+1]=p1; pl[2*tid]=q0; pl[2*tid+1]=q1;
}

extern "C" void kernel_launch(void* const* d_in, const int* in_sizes, int n_in,
                              void* d_out, int out_size)
{
    const float* s          = (const float*)d_in[0];
    const float* W_in       = (const float*)d_in[1];
    const float* in_norm_w  = (const float*)d_in[2];
    const float* Wr         = (const float*)d_in[3];
    const float* expert_bias= (const float*)d_in[4];
    const float* Wg         = (const float*)d_in[5];
    const float* Wu         = (const float*)d_in[6];
    const float* Wd         = (const float*)d_in[7];
    const float* enorm_w    = (const float*)d_in[8];
    const float* out_norm_w = (const float*)d_in[9];
    const float* W_out      = (const float*)d_in[10];
    float* out = (float*)d_out;

    cudaFuncSetAttribute(mm_kernel<0,0,0>, cudaFuncAttributeMaxDynamicSharedMemorySize, SMEM_DYN);
    cudaFuncSetAttribute(mm_kernel<1,1,1>, cudaFuncAttributeMaxDynamicSharedMemorySize, SMEM_DYN);
    cudaFuncSetAttribute(mm_kernel<0,1,0>, cudaFuncAttributeMaxDynamicSharedMemorySize, SMEM_DYN);

    void* p;
    #define SYM(v,T,sname) cudaGetSymbolAddress(&p,sname); T* v=(T*)p;
    SYM(h_ptr,float,g_h) SYM(Oe_ptr,float,g_Oe)
    SYM(sH,bf,g_sH) SYM(sL,bf,g_sL) SYM(hH,bf,g_hH) SYM(hL,bf,g_hL)
    SYM(yH,bf,g_yH) SYM(yL,bf,g_yL) SYM(TH,bf,g_TH) SYM(TL,bf,g_TL)
    SYM(WinH,bf,g_WinH) SYM(WinL,bf,g_WinL)
    SYM(WgH,bf,g_WgH) SYM(WgL,bf,g_WgL) SYM(WuH,bf,g_WuH) SYM(WuL,bf,g_WuL)
    SYM(WdH,bf,g_WdH) SYM(WdL,bf,g_WdL) SYM(WoH,bf,g_WoH) SYM(WoL,bf,g_WoL)
    SYM(off_ptr,int,g_off) SYM(ptok,int,g_pairtok)
    #undef SYM

    init_counts<<<1,32>>>();
    int nW = DMODEL*DMODEL/4, nE = NEXP*DFF*DMODEL/4;
    convert_hilo<<<(N_TOK*DMODEL/4+255)/256,256>>>(s, sH, sL, N_TOK*DMODEL/4);
    convert_hilo<<<(nW+255)/256,256>>>(W_in, WinH, WinL, nW);
    convert_hilo<<<(nE+255)/256,256>>>(Wg, WgH, WgL, nE);
    convert_hilo<<<(nE+255)/256,256>>>(Wu, WuH, WuL, nE);
    convert_hilo<<<(nE+255)/256,256>>>(Wd, WdH, WdL, nE);
    convert_hilo<<<(nW+255)/256,256>>>(W_out, WoH, WoL, nW);

    // h_pre = s @ W_in^T
    mm_kernel<0,0,0><<<dim3(N_TOK/128, DMODEL/128, 1), 256, SMEM_DYN>>>(
        sH, sL, WinH, WinL, nullptr, nullptr, h_ptr, nullptr, nullptr,
        N_TOK, DMODEL, DMODEL, nullptr, nullptr, 0);
    rmsnorm_hilo<<<N_TOK,256>>>(h_ptr, in_norm_w, h_ptr, hH, hL);
    router_kernel<<<(N_TOK*32)/256,256>>>(h_ptr, Wr, expert_bias);
    scan_offsets<<<1,32>>>();
    scatter_pairs<<<N_TOK/256,256>>>();

    // T = silu(h Wg^T) * (h Wu^T)  (gathered, grouped, dual-B)
    mm_kernel<1,1,1><<<dim3(NPAIR/128, DFF/64, NEXP), 256, SMEM_DYN>>>(
        hH, hL, WgH, WgL, WuH, WuL, nullptr, TH, TL,
        0, DMODEL, DFF, off_ptr, ptok, (ll)DFF*DMODEL);

    // Oe = T @ Wd^T (grouped)
    mm_kernel<0,1,0><<<dim3(NPAIR/128, DMODEL/128, NEXP), 256, SMEM_DYN>>>(
        TH, TL, WdH, WdL, nullptr, nullptr, Oe_ptr, nullptr, nullptr,
        0, DFF, DMODEL, off_ptr, nullptr, (ll)DMODEL*DFF);

    combine_rows<<<N_TOK,256>>>(enorm_w, out_norm_w);

    // out = y @ W_out^T
    mm_kernel<0,0,0><<<dim3(N_TOK/128, DMODEL/128, 1), 256, SMEM_DYN>>>(
        yH, yL, WoH, WoL, nullptr, nullptr, out, nullptr, nullptr,
        N_TOK, DMODEL, DMODEL, nullptr, nullptr, 0);
}